// round 9
// baseline (speedup 1.0000x reference)
#include <cuda_runtime.h>
#include <cuda_fp16.h>
#include <cstdint>

// Conv2d 3x3 s1 p1: x[256,224,224] f32, w[256,256,3,3] f32 -> out[256,224,224] f32
// Winograd F(2x2,3x3) on fp16 tensor cores (mma.sync m16n8k16, f32 acc).
// Round 9: inverse transform FUSED into GEMM epilogue (k-outer loop, y
// accumulated in registers). No M tensor, no wino_out kernel.

#define H 224
#define W 224
#define C 256
#define NTILE 12544          // 112*112 output tiles of 2x2
#define TW 112               // tiles per image row

// U: [k(16)][ci(256)][tile(12544)] fp16  (103 MB)
__device__ __align__(16) __half g_U[16ull * C * NTILE];
// W': [k(16)][coh(2)][kc(8)][co(128)][j(32)] fp16, ci = kc*32+j  (2 MB)
__device__ __align__(16) __half g_Wt[16ull * 2 * 8 * 128 * 32];

// ---------------- weight transform: W' = G w G^T ----------------
__global__ void wino_w_kernel(const float* __restrict__ w) {
    int i = blockIdx.x * blockDim.x + threadIdx.x;   // 65536 = co*ci
    if (i >= C * C) return;
    int ci = i & 255;
    int co = i >> 8;
    float g[3][3];
#pragma unroll
    for (int r = 0; r < 3; ++r)
#pragma unroll
        for (int c = 0; c < 3; ++c)
            g[r][c] = w[((co * C + ci) * 3 + r) * 3 + c];
    float t[4][3];
#pragma unroll
    for (int c = 0; c < 3; ++c) {
        t[0][c] = g[0][c];
        t[1][c] = 0.5f * (g[0][c] + g[1][c] + g[2][c]);
        t[2][c] = 0.5f * (g[0][c] - g[1][c] + g[2][c]);
        t[3][c] = g[2][c];
    }
    float u[4][4];
#pragma unroll
    for (int r = 0; r < 4; ++r) {
        u[r][0] = t[r][0];
        u[r][1] = 0.5f * (t[r][0] + t[r][1] + t[r][2]);
        u[r][2] = 0.5f * (t[r][0] - t[r][1] + t[r][2]);
        u[r][3] = t[r][2];
    }
    int coh = co >> 7, col = co & 127, kc = ci >> 5, j = ci & 31;
#pragma unroll
    for (int k = 0; k < 16; ++k)
        g_Wt[((((size_t)(k * 2 + coh) * 8 + kc) * 128 + col) << 5) + j] =
            __float2half_rn(u[k >> 2][k & 3]);
}

// ---------------- input transform: U = B^T d B, 2 tiles per thread ----------
__global__ void wino_in_kernel(const float* __restrict__ x) {
    int p = blockIdx.x * 128 + threadIdx.x;    // 0..6271 tile-pairs, grid.x = 49
    int ci = blockIdx.y;
    int ty = p / 56, px = p - ty * 56;
    int tx0 = px * 2;
    int y0 = 2 * ty - 1, x0 = 2 * tx0 - 1;
    const float* xp = x + (size_t)ci * H * W;
    float d[4][6];
#pragma unroll
    for (int r = 0; r < 4; ++r) {
        int yy = y0 + r;
        bool yok = (unsigned)yy < 224u;
        const float* row = xp + yy * W;
#pragma unroll
        for (int c = 0; c < 6; ++c) {
            int xx = x0 + c;
            d[r][c] = (yok && (unsigned)xx < 224u) ? row[xx] : 0.0f;
        }
    }
    float tr[4][6];
#pragma unroll
    for (int c = 0; c < 6; ++c) {
        tr[0][c] = d[0][c] - d[2][c];
        tr[1][c] = d[1][c] + d[2][c];
        tr[2][c] = d[2][c] - d[1][c];
        tr[3][c] = d[1][c] - d[3][c];
    }
    size_t t0 = (size_t)ty * TW + tx0;
#pragma unroll
    for (int r = 0; r < 4; ++r) {
        float ua[4], ub[4];
        ua[0] = tr[r][0] - tr[r][2];
        ua[1] = tr[r][1] + tr[r][2];
        ua[2] = tr[r][2] - tr[r][1];
        ua[3] = tr[r][1] - tr[r][3];
        ub[0] = tr[r][2] - tr[r][4];
        ub[1] = tr[r][3] + tr[r][4];
        ub[2] = tr[r][4] - tr[r][3];
        ub[3] = tr[r][3] - tr[r][5];
#pragma unroll
        for (int c = 0; c < 4; ++c) {
            int k = r * 4 + c;
            *(__half2*)&g_U[(size_t)(k * C + ci) * NTILE + t0] =
                __floats2half2_rn(ua[c], ub[c]);
        }
    }
}

// ---------------- fused GEMM + inverse transform ----------------
__device__ __forceinline__ uint32_t smem_u32(const void* p) {
    uint32_t a;
    asm("{ .reg .u64 t; cvta.to.shared.u64 t, %1; cvt.u32.u64 %0, t; }" : "=r"(a) : "l"(p));
    return a;
}
__device__ __forceinline__ void cp16(uint32_t dst, const void* src) {
    asm volatile("cp.async.cg.shared.global [%0], [%1], 16;" :: "r"(dst), "l"(src) : "memory");
}
__device__ __forceinline__ void cp_commit() {
    asm volatile("cp.async.commit_group;" ::: "memory");
}
__device__ __forceinline__ void ldsm_x4(uint32_t* r, uint32_t a) {
    asm volatile("ldmatrix.sync.aligned.m8n8.x4.shared.b16 {%0,%1,%2,%3}, [%4];"
                 : "=r"(r[0]), "=r"(r[1]), "=r"(r[2]), "=r"(r[3]) : "r"(a));
}
__device__ __forceinline__ void ldsm_x2t(uint32_t* r, uint32_t a) {
    asm volatile("ldmatrix.sync.aligned.m8n8.x2.trans.shared.b16 {%0,%1}, [%2];"
                 : "=r"(r[0]), "=r"(r[1]) : "r"(a));
}
__device__ __forceinline__ void mma16816(float* d, const uint32_t* a, const uint32_t* b) {
    asm volatile(
        "mma.sync.aligned.m16n8k16.row.col.f32.f16.f16.f32 "
        "{%0,%1,%2,%3}, {%4,%5,%6,%7}, {%8,%9}, {%0,%1,%2,%3};"
        : "+f"(d[0]), "+f"(d[1]), "+f"(d[2]), "+f"(d[3])
        : "r"(a[0]), "r"(a[1]), "r"(a[2]), "r"(a[3]), "r"(b[0]), "r"(b[1]));
}

#define A_BYTES 10240                    // 128 rows * 80B (64 used)
#define B_BYTES 2560                     // 32 rows * 80B (64 used = 32 tiles)
#define STAGE_BYTES (A_BYTES + B_BYTES)  // 12800
#define NBUF 4
#define SMEM_SZ (NBUF * STAGE_BYTES)     // 51200
#define NSTAGE 128                       // 16 k * 8 kc

__device__ __forceinline__ void load_stage(int s, uint32_t sbase, int tid,
                                           int coh, int tb) {
    int k  = s >> 3;
    int kc = s & 7;
    const __half* wsrc = g_Wt + (((size_t)(k * 2 + coh) * 8 + kc) << 12);
    // A: 512 x 16B contiguous
#pragma unroll
    for (int v = tid; v < 512; v += 256) {
        cp16(sbase + (v >> 2) * 80 + (v & 3) * 16, (const char*)wsrc + v * 16);
    }
    // B: 128 x 16B — 32 ci rows x 64B (32 tiles fp16)
    uint32_t bbase = sbase + A_BYTES;
    const __half* usrc = g_U + (size_t)(k * C + kc * 32) * NTILE + tb * 32;
    if (tid < 128) {
        int row = tid >> 2;
        int cv  = tid & 3;
        cp16(bbase + row * 80 + cv * 16,
             (const char*)(usrc + (size_t)row * NTILE) + cv * 16);
    }
}

__global__ __launch_bounds__(256, 2) void wino_fused_kernel(float* __restrict__ out) {
    extern __shared__ __align__(16) unsigned char smbuf[];
    const uint32_t sb = smem_u32(smbuf);
    const int tid  = threadIdx.x;
    const int lane = tid & 31;
    const int wid  = tid >> 5;
    const int wm   = wid & 3;       // 4 M-warps x 32 co
    const int wn   = wid >> 2;      // 2 N-warps x 16 tiles
    const int tb   = blockIdx.x;    // 0..391 (32-tile blocks)
    const int coh  = blockIdx.y;

    // y accumulators: [m][n][q] slot -> 4 output pixels (2x2)
    float yac[2][2][4][4];
#pragma unroll
    for (int m = 0; m < 2; ++m)
#pragma unroll
        for (int n = 0; n < 2; ++n)
#pragma unroll
            for (int q = 0; q < 4; ++q)
#pragma unroll
                for (int e = 0; e < 4; ++e) yac[m][n][q][e] = 0.0f;

    load_stage(0, sb, tid, coh, tb);
    cp_commit();
    load_stage(1, sb + STAGE_BYTES, tid, coh, tb);
    cp_commit();
    load_stage(2, sb + 2 * STAGE_BYTES, tid, coh, tb);
    cp_commit();

    for (int k = 0; k < 16; ++k) {
        float acc[2][2][4];
#pragma unroll
        for (int m = 0; m < 2; ++m)
#pragma unroll
            for (int n = 0; n < 2; ++n)
#pragma unroll
                for (int q = 0; q < 4; ++q) acc[m][n][q] = 0.0f;

        for (int kc = 0; kc < 8; ++kc) {
            int s = k * 8 + kc;
            asm volatile("cp.async.wait_group 2;" ::: "memory");
            __syncthreads();
            if (s + 3 < NSTAGE)
                load_stage(s + 3, sb + ((s + 3) & 3) * STAGE_BYTES, tid, coh, tb);
            cp_commit();

            const uint32_t As = sb + (s & 3) * STAGE_BYTES;
            const uint32_t Bs = As + A_BYTES;
            uint32_t aA[2], aB[2];
#pragma unroll
            for (int m = 0; m < 2; ++m)
                aA[m] = As + (wm * 32 + m * 16 + (lane & 15)) * 80 + (lane >> 4) * 16;
#pragma unroll
            for (int n = 0; n < 2; ++n)
                aB[n] = Bs + (lane & 15) * 80 + wn * 32 + n * 16;

#pragma unroll
            for (int ks = 0; ks < 2; ++ks) {
                uint32_t a[2][4], b[2][2];
#pragma unroll
                for (int m = 0; m < 2; ++m) ldsm_x4(a[m], aA[m] + ks * 32);
#pragma unroll
                for (int n = 0; n < 2; ++n) ldsm_x2t(b[n], aB[n] + ks * 16 * 80);
#pragma unroll
                for (int m = 0; m < 2; ++m)
#pragma unroll
                    for (int n = 0; n < 2; ++n) mma16816(acc[m][n], a[m], b[n]);
            }
        }

        // fold component k into the 2x2 outputs: y[i][j] += At[i][kr]*At[j][kcc]*M
        int kr  = k >> 2;
        int kcc = k & 3;
        float a0 = (kr == 3)  ? 0.0f : 1.0f;
        float a1 = (kr == 0)  ? 0.0f : ((kr == 1) ? 1.0f : -1.0f);
        float b0 = (kcc == 3) ? 0.0f : 1.0f;
        float b1 = (kcc == 0) ? 0.0f : ((kcc == 1) ? 1.0f : -1.0f);
#pragma unroll
        for (int m = 0; m < 2; ++m)
#pragma unroll
            for (int n = 0; n < 2; ++n)
#pragma unroll
                for (int q = 0; q < 4; ++q) {
                    float Mv = acc[m][n][q];
                    float t0 = a0 * Mv, t1 = a1 * Mv;
                    yac[m][n][q][0] += t0 * b0;
                    yac[m][n][q][1] += t0 * b1;
                    yac[m][n][q][2] += t1 * b0;
                    yac[m][n][q][3] += t1 * b1;
                }
    }

    // epilogue: write 2x2 outputs for each (co, tile) slot
    const int rq = lane >> 2;
    const int cq = (lane & 3) * 2;
#pragma unroll
    for (int m = 0; m < 2; ++m)
#pragma unroll
        for (int n = 0; n < 2; ++n)
#pragma unroll
            for (int q = 0; q < 4; ++q) {
                int co   = coh * 128 + wm * 32 + m * 16 + rq + ((q >> 1) << 3);
                int tile = tb * 32 + wn * 16 + n * 8 + cq + (q & 1);
                int ty = tile / TW, tx = tile - ty * TW;
                float* p = out + ((size_t)co * H + 2 * ty) * W + 2 * tx;
                *(float2*)p       = make_float2(yac[m][n][q][0], yac[m][n][q][1]);
                *(float2*)(p + W) = make_float2(yac[m][n][q][2], yac[m][n][q][3]);
            }
}

extern "C" void kernel_launch(void* const* d_in, const int* in_sizes, int n_in,
                              void* d_out, int out_size) {
    const float* x = (const float*)d_in[0];   // [1,256,224,224]
    const float* w = (const float*)d_in[1];   // [256,256,3,3]
    float* out = (float*)d_out;               // [256,224,224]
    (void)in_sizes; (void)n_in; (void)out_size;

    wino_w_kernel<<<(C * C + 255) / 256, 256>>>(w);
    wino_in_kernel<<<dim3(49, C), 128>>>(x);

    static int smem_set = 0;
    if (!smem_set) {
        cudaFuncSetAttribute(wino_fused_kernel,
                             cudaFuncAttributeMaxDynamicSharedMemorySize, SMEM_SZ);
        smem_set = 1;
    }
    wino_fused_kernel<<<dim3(NTILE / 32, 2), 256, SMEM_SZ>>>(out);
}

// round 10
// speedup vs baseline: 1.0284x; 1.0284x over previous
#include <cuda_runtime.h>
#include <cuda_fp16.h>
#include <cstdint>

// Conv2d 3x3 s1 p1: x[256,224,224] f32, w[256,256,3,3] f32 -> out[256,224,224] f32
// Winograd F(2x2,3x3) on fp16 tensor cores (mma.sync m16n8k16, f32 acc).
// Round 10: fused inverse transform (k-outer, y in registers) with FAT stages:
// CTA tile M=128 co x N=64 tiles, warp = 32co x 32tiles, 1 CTA/SM (~200 regs).

#define H 224
#define W 224
#define C 256
#define NTILE 12544          // 112*112 output tiles of 2x2
#define TW 112               // tiles per image row

// U: [k(16)][ci(256)][tile(12544)] fp16  (103 MB)
__device__ __align__(16) __half g_U[16ull * C * NTILE];
// W': [k(16)][coh(2)][kc(8)][co(128)][j(32)] fp16, ci = kc*32+j  (2 MB)
__device__ __align__(16) __half g_Wt[16ull * 2 * 8 * 128 * 32];

// ---------------- weight transform: W' = G w G^T ----------------
__global__ void wino_w_kernel(const float* __restrict__ w) {
    int i = blockIdx.x * blockDim.x + threadIdx.x;   // 65536 = co*ci
    if (i >= C * C) return;
    int ci = i & 255;
    int co = i >> 8;
    float g[3][3];
#pragma unroll
    for (int r = 0; r < 3; ++r)
#pragma unroll
        for (int c = 0; c < 3; ++c)
            g[r][c] = w[((co * C + ci) * 3 + r) * 3 + c];
    float t[4][3];
#pragma unroll
    for (int c = 0; c < 3; ++c) {
        t[0][c] = g[0][c];
        t[1][c] = 0.5f * (g[0][c] + g[1][c] + g[2][c]);
        t[2][c] = 0.5f * (g[0][c] - g[1][c] + g[2][c]);
        t[3][c] = g[2][c];
    }
    float u[4][4];
#pragma unroll
    for (int r = 0; r < 4; ++r) {
        u[r][0] = t[r][0];
        u[r][1] = 0.5f * (t[r][0] + t[r][1] + t[r][2]);
        u[r][2] = 0.5f * (t[r][0] - t[r][1] + t[r][2]);
        u[r][3] = t[r][2];
    }
    int coh = co >> 7, col = co & 127, kc = ci >> 5, j = ci & 31;
#pragma unroll
    for (int k = 0; k < 16; ++k)
        g_Wt[((((size_t)(k * 2 + coh) * 8 + kc) * 128 + col) << 5) + j] =
            __float2half_rn(u[k >> 2][k & 3]);
}

// ---------------- input transform: U = B^T d B, 2 tiles per thread ----------
__global__ void wino_in_kernel(const float* __restrict__ x) {
    int p = blockIdx.x * 128 + threadIdx.x;    // 0..6271 tile-pairs, grid.x = 49
    int ci = blockIdx.y;
    int ty = p / 56, px = p - ty * 56;
    int tx0 = px * 2;
    int y0 = 2 * ty - 1, x0 = 2 * tx0 - 1;
    const float* xp = x + (size_t)ci * H * W;
    float d[4][6];
#pragma unroll
    for (int r = 0; r < 4; ++r) {
        int yy = y0 + r;
        bool yok = (unsigned)yy < 224u;
        const float* row = xp + yy * W;
#pragma unroll
        for (int c = 0; c < 6; ++c) {
            int xx = x0 + c;
            d[r][c] = (yok && (unsigned)xx < 224u) ? row[xx] : 0.0f;
        }
    }
    float tr[4][6];
#pragma unroll
    for (int c = 0; c < 6; ++c) {
        tr[0][c] = d[0][c] - d[2][c];
        tr[1][c] = d[1][c] + d[2][c];
        tr[2][c] = d[2][c] - d[1][c];
        tr[3][c] = d[1][c] - d[3][c];
    }
    size_t t0 = (size_t)ty * TW + tx0;
#pragma unroll
    for (int r = 0; r < 4; ++r) {
        float ua[4], ub[4];
        ua[0] = tr[r][0] - tr[r][2];
        ua[1] = tr[r][1] + tr[r][2];
        ua[2] = tr[r][2] - tr[r][1];
        ua[3] = tr[r][1] - tr[r][3];
        ub[0] = tr[r][2] - tr[r][4];
        ub[1] = tr[r][3] + tr[r][4];
        ub[2] = tr[r][4] - tr[r][3];
        ub[3] = tr[r][3] - tr[r][5];
#pragma unroll
        for (int c = 0; c < 4; ++c) {
            int k = r * 4 + c;
            *(__half2*)&g_U[(size_t)(k * C + ci) * NTILE + t0] =
                __floats2half2_rn(ua[c], ub[c]);
        }
    }
}

// ---------------- fused GEMM + inverse transform ----------------
__device__ __forceinline__ uint32_t smem_u32(const void* p) {
    uint32_t a;
    asm("{ .reg .u64 t; cvta.to.shared.u64 t, %1; cvt.u32.u64 %0, t; }" : "=r"(a) : "l"(p));
    return a;
}
__device__ __forceinline__ void cp16(uint32_t dst, const void* src) {
    asm volatile("cp.async.cg.shared.global [%0], [%1], 16;" :: "r"(dst), "l"(src) : "memory");
}
__device__ __forceinline__ void cp_commit() {
    asm volatile("cp.async.commit_group;" ::: "memory");
}
__device__ __forceinline__ void ldsm_x4(uint32_t* r, uint32_t a) {
    asm volatile("ldmatrix.sync.aligned.m8n8.x4.shared.b16 {%0,%1,%2,%3}, [%4];"
                 : "=r"(r[0]), "=r"(r[1]), "=r"(r[2]), "=r"(r[3]) : "r"(a));
}
__device__ __forceinline__ void ldsm_x2t(uint32_t* r, uint32_t a) {
    asm volatile("ldmatrix.sync.aligned.m8n8.x2.trans.shared.b16 {%0,%1}, [%2];"
                 : "=r"(r[0]), "=r"(r[1]) : "r"(a));
}
__device__ __forceinline__ void mma16816(float* d, const uint32_t* a, const uint32_t* b) {
    asm volatile(
        "mma.sync.aligned.m16n8k16.row.col.f32.f16.f16.f32 "
        "{%0,%1,%2,%3}, {%4,%5,%6,%7}, {%8,%9}, {%0,%1,%2,%3};"
        : "+f"(d[0]), "+f"(d[1]), "+f"(d[2]), "+f"(d[3])
        : "r"(a[0]), "r"(a[1]), "r"(a[2]), "r"(a[3]), "r"(b[0]), "r"(b[1]));
}

#define A_BYTES 10240                    // 128 rows * 80B (64 used)
#define B_STRIDE 144                     // 128B data + 16 pad (odd multiple of 16)
#define B_BYTES (32 * B_STRIDE)          // 4608 (32 ci rows x 64 tiles fp16)
#define STAGE_BYTES (A_BYTES + B_BYTES)  // 14848
#define NBUF 4
#define SMEM_SZ (NBUF * STAGE_BYTES)     // 59392
#define NSTAGE 128                       // 16 k * 8 kc

__device__ __forceinline__ void load_stage(int s, uint32_t sbase, int tid,
                                           int coh, int tb) {
    int k  = s >> 3;
    int kc = s & 7;
    const __half* wsrc = g_Wt + (((size_t)(k * 2 + coh) * 8 + kc) << 12);
    // A: 512 x 16B contiguous (2 per thread)
#pragma unroll
    for (int v = tid; v < 512; v += 256) {
        cp16(sbase + (v >> 2) * 80 + (v & 3) * 16, (const char*)wsrc + v * 16);
    }
    // B: 256 x 16B — 32 ci rows x 128B (64 tiles fp16), 1 per thread
    uint32_t bbase = sbase + A_BYTES;
    const __half* usrc = g_U + (size_t)(k * C + kc * 32) * NTILE + tb * 64;
    {
        int row = tid >> 3;
        int cv  = tid & 7;
        cp16(bbase + row * B_STRIDE + cv * 16,
             (const char*)(usrc + (size_t)row * NTILE) + cv * 16);
    }
}

__global__ __launch_bounds__(256, 1) void wino_fused_kernel(float* __restrict__ out) {
    extern __shared__ __align__(16) unsigned char smbuf[];
    const uint32_t sb = smem_u32(smbuf);
    const int tid  = threadIdx.x;
    const int lane = tid & 31;
    const int wid  = tid >> 5;
    const int wm   = wid & 3;       // 4 M-warps x 32 co
    const int wn   = wid >> 2;      // 2 N-warps x 32 tiles
    const int tb   = blockIdx.x;    // 0..195 (64-tile blocks)
    const int coh  = blockIdx.y;

    // y accumulators: [m][n][q] slot -> 4 output pixels (2x2)
    float yac[2][4][4][4];
#pragma unroll
    for (int m = 0; m < 2; ++m)
#pragma unroll
        for (int n = 0; n < 4; ++n)
#pragma unroll
            for (int q = 0; q < 4; ++q)
#pragma unroll
                for (int e = 0; e < 4; ++e) yac[m][n][q][e] = 0.0f;

    load_stage(0, sb, tid, coh, tb);
    cp_commit();
    load_stage(1, sb + STAGE_BYTES, tid, coh, tb);
    cp_commit();
    load_stage(2, sb + 2 * STAGE_BYTES, tid, coh, tb);
    cp_commit();

    for (int k = 0; k < 16; ++k) {
        float acc[2][4][4];
#pragma unroll
        for (int m = 0; m < 2; ++m)
#pragma unroll
            for (int n = 0; n < 4; ++n)
#pragma unroll
                for (int q = 0; q < 4; ++q) acc[m][n][q] = 0.0f;

        for (int kc = 0; kc < 8; ++kc) {
            int s = k * 8 + kc;
            asm volatile("cp.async.wait_group 2;" ::: "memory");
            __syncthreads();
            if (s + 3 < NSTAGE)
                load_stage(s + 3, sb + ((s + 3) & 3) * STAGE_BYTES, tid, coh, tb);
            cp_commit();

            const uint32_t As = sb + (s & 3) * STAGE_BYTES;
            const uint32_t Bs = As + A_BYTES;
            uint32_t aA[2], aB[4];
#pragma unroll
            for (int m = 0; m < 2; ++m)
                aA[m] = As + (wm * 32 + m * 16 + (lane & 15)) * 80 + (lane >> 4) * 16;
#pragma unroll
            for (int n = 0; n < 4; ++n)
                aB[n] = Bs + (lane & 15) * B_STRIDE + wn * 64 + n * 16;

#pragma unroll
            for (int ks = 0; ks < 2; ++ks) {
                uint32_t a[2][4], b[4][2];
#pragma unroll
                for (int m = 0; m < 2; ++m) ldsm_x4(a[m], aA[m] + ks * 32);
#pragma unroll
                for (int n = 0; n < 4; ++n) ldsm_x2t(b[n], aB[n] + ks * 16 * B_STRIDE);
#pragma unroll
                for (int m = 0; m < 2; ++m)
#pragma unroll
                    for (int n = 0; n < 4; ++n) mma16816(acc[m][n], a[m], b[n]);
            }
        }

        // fold component k into the 2x2 outputs: y[i][j] += At[i][kr]*At[j][kcc]*M
        int kr  = k >> 2;
        int kcc = k & 3;
        float a0 = (kr == 3)  ? 0.0f : 1.0f;
        float a1 = (kr == 0)  ? 0.0f : ((kr == 1) ? 1.0f : -1.0f);
        float b0 = (kcc == 3) ? 0.0f : 1.0f;
        float b1 = (kcc == 0) ? 0.0f : ((kcc == 1) ? 1.0f : -1.0f);
#pragma unroll
        for (int m = 0; m < 2; ++m)
#pragma unroll
            for (int n = 0; n < 4; ++n)
#pragma unroll
                for (int q = 0; q < 4; ++q) {
                    float Mv = acc[m][n][q];
                    float t0 = a0 * Mv, t1 = a1 * Mv;
                    yac[m][n][q][0] += t0 * b0;
                    yac[m][n][q][1] += t0 * b1;
                    yac[m][n][q][2] += t1 * b0;
                    yac[m][n][q][3] += t1 * b1;
                }
    }

    // epilogue: write 2x2 outputs for each (co, tile) slot
    const int rq = lane >> 2;
    const int cq = (lane & 3) * 2;
#pragma unroll
    for (int m = 0; m < 2; ++m)
#pragma unroll
        for (int n = 0; n < 4; ++n)
#pragma unroll
            for (int q = 0; q < 4; ++q) {
                int co   = coh * 128 + wm * 32 + m * 16 + rq + ((q >> 1) << 3);
                int tile = tb * 64 + wn * 32 + n * 8 + cq + (q & 1);
                int ty = tile / TW, tx = tile - ty * TW;
                float* p = out + ((size_t)co * H + 2 * ty) * W + 2 * tx;
                *(float2*)p       = make_float2(yac[m][n][q][0], yac[m][n][q][1]);
                *(float2*)(p + W) = make_float2(yac[m][n][q][2], yac[m][n][q][3]);
            }
}

extern "C" void kernel_launch(void* const* d_in, const int* in_sizes, int n_in,
                              void* d_out, int out_size) {
    const float* x = (const float*)d_in[0];   // [1,256,224,224]
    const float* w = (const float*)d_in[1];   // [256,256,3,3]
    float* out = (float*)d_out;               // [256,224,224]
    (void)in_sizes; (void)n_in; (void)out_size;

    wino_w_kernel<<<(C * C + 255) / 256, 256>>>(w);
    wino_in_kernel<<<dim3(49, C), 128>>>(x);

    static int smem_set = 0;
    if (!smem_set) {
        cudaFuncSetAttribute(wino_fused_kernel,
                             cudaFuncAttributeMaxDynamicSharedMemorySize, SMEM_SZ);
        smem_set = 1;
    }
    wino_fused_kernel<<<dim3(NTILE / 64, 2), 256, SMEM_SZ>>>(out);
}

// round 13
// speedup vs baseline: 1.2380x; 1.2038x over previous
#include <cuda_runtime.h>
#include <cuda_fp16.h>
#include <cstdint>
#include <cstring>

// Conv2d 3x3 s1 p1: x[256,224,224] f32, w[256,256,3,3] f32 -> out[256,224,224] f32
// Winograd F(2x2,3x3) on fp16 tensor cores (mma.sync m16n8k16, f32 acc).
// Round 13 (= round 12 + epilogue col-units fix): round-8 structure (2 CTA/SM,
// N=112) + 2 k-components per CTA + smem-staged coalesced M epilogue +
// 3-buffer pipeline with hoisted fragment addresses.

#define H 224
#define W 224
#define C 256
#define NTILE 12544          // 112*112 output tiles of 2x2
#define TW 112               // tiles per image row

// U: [k(16)][ci(256)][tile(12544)] fp16  (98 MB)
__device__ __align__(16) __half g_U[16ull * C * NTILE];
// M: [k(16)][co(256)][tile(12544)] fp16  (98 MB)
__device__ __align__(16) __half g_M[16ull * C * NTILE];
// W': [k(16)][coh(2)][kc(8)][co(128)][j(32)] fp16, ci = kc*32+j  (2 MB)
__device__ __align__(16) __half g_Wt[16ull * 2 * 8 * 128 * 32];

__device__ __forceinline__ uint32_t h2_as_u32(__half2 v) {
    uint32_t u;
    memcpy(&u, &v, 4);
    return u;
}

// ---------------- weight transform: W' = G w G^T ----------------
__global__ void wino_w_kernel(const float* __restrict__ w) {
    int i = blockIdx.x * blockDim.x + threadIdx.x;   // 65536 = co*ci
    if (i >= C * C) return;
    int ci = i & 255;
    int co = i >> 8;
    float g[3][3];
#pragma unroll
    for (int r = 0; r < 3; ++r)
#pragma unroll
        for (int c = 0; c < 3; ++c)
            g[r][c] = w[((co * C + ci) * 3 + r) * 3 + c];
    float t[4][3];
#pragma unroll
    for (int c = 0; c < 3; ++c) {
        t[0][c] = g[0][c];
        t[1][c] = 0.5f * (g[0][c] + g[1][c] + g[2][c]);
        t[2][c] = 0.5f * (g[0][c] - g[1][c] + g[2][c]);
        t[3][c] = g[2][c];
    }
    float u[4][4];
#pragma unroll
    for (int r = 0; r < 4; ++r) {
        u[r][0] = t[r][0];
        u[r][1] = 0.5f * (t[r][0] + t[r][1] + t[r][2]);
        u[r][2] = 0.5f * (t[r][0] - t[r][1] + t[r][2]);
        u[r][3] = t[r][2];
    }
    int coh = co >> 7, col = co & 127, kc = ci >> 5, j = ci & 31;
#pragma unroll
    for (int k = 0; k < 16; ++k)
        g_Wt[((((size_t)(k * 2 + coh) * 8 + kc) * 128 + col) << 5) + j] =
            __float2half_rn(u[k >> 2][k & 3]);
}

// ---------------- input transform: U = B^T d B, 2 tiles per thread ----------
__global__ void wino_in_kernel(const float* __restrict__ x) {
    int p = blockIdx.x * 128 + threadIdx.x;    // 0..6271 tile-pairs, grid.x = 49
    int ci = blockIdx.y;
    int ty = p / 56, px = p - ty * 56;
    int tx0 = px * 2;
    int y0 = 2 * ty - 1, x0 = 2 * tx0 - 1;
    const float* xp = x + (size_t)ci * H * W;
    float d[4][6];
#pragma unroll
    for (int r = 0; r < 4; ++r) {
        int yy = y0 + r;
        bool yok = (unsigned)yy < 224u;
        const float* row = xp + yy * W;
#pragma unroll
        for (int c = 0; c < 6; ++c) {
            int xx = x0 + c;
            d[r][c] = (yok && (unsigned)xx < 224u) ? row[xx] : 0.0f;
        }
    }
    float tr[4][6];
#pragma unroll
    for (int c = 0; c < 6; ++c) {
        tr[0][c] = d[0][c] - d[2][c];
        tr[1][c] = d[1][c] + d[2][c];
        tr[2][c] = d[2][c] - d[1][c];
        tr[3][c] = d[1][c] - d[3][c];
    }
    size_t t0 = (size_t)ty * TW + tx0;
#pragma unroll
    for (int r = 0; r < 4; ++r) {
        float ua[4], ub[4];
        ua[0] = tr[r][0] - tr[r][2];
        ua[1] = tr[r][1] + tr[r][2];
        ua[2] = tr[r][2] - tr[r][1];
        ua[3] = tr[r][1] - tr[r][3];
        ub[0] = tr[r][2] - tr[r][4];
        ub[1] = tr[r][3] + tr[r][4];
        ub[2] = tr[r][4] - tr[r][3];
        ub[3] = tr[r][3] - tr[r][5];
#pragma unroll
        for (int c = 0; c < 4; ++c) {
            int k = r * 4 + c;
            *(__half2*)&g_U[(size_t)(k * C + ci) * NTILE + t0] =
                __floats2half2_rn(ua[c], ub[c]);
        }
    }
}

// ---------------- batched component GEMMs ----------------
__device__ __forceinline__ uint32_t smem_u32(const void* p) {
    uint32_t a;
    asm("{ .reg .u64 t; cvta.to.shared.u64 t, %1; cvt.u32.u64 %0, t; }" : "=r"(a) : "l"(p));
    return a;
}
__device__ __forceinline__ void cp16(uint32_t dst, const void* src) {
    asm volatile("cp.async.cg.shared.global [%0], [%1], 16;" :: "r"(dst), "l"(src) : "memory");
}
__device__ __forceinline__ void cp_commit() {
    asm volatile("cp.async.commit_group;" ::: "memory");
}
__device__ __forceinline__ void ldsm_x4(uint32_t* r, uint32_t a) {
    asm volatile("ldmatrix.sync.aligned.m8n8.x4.shared.b16 {%0,%1,%2,%3}, [%4];"
                 : "=r"(r[0]), "=r"(r[1]), "=r"(r[2]), "=r"(r[3]) : "r"(a));
}
__device__ __forceinline__ void ldsm_x2t(uint32_t* r, uint32_t a) {
    asm volatile("ldmatrix.sync.aligned.m8n8.x2.trans.shared.b16 {%0,%1}, [%2];"
                 : "=r"(r[0]), "=r"(r[1]) : "r"(a));
}
__device__ __forceinline__ void mma16816(float* d, const uint32_t* a, const uint32_t* b) {
    asm volatile(
        "mma.sync.aligned.m16n8k16.row.col.f32.f16.f16.f32 "
        "{%0,%1,%2,%3}, {%4,%5,%6,%7}, {%8,%9}, {%0,%1,%2,%3};"
        : "+f"(d[0]), "+f"(d[1]), "+f"(d[2]), "+f"(d[3])
        : "r"(a[0]), "r"(a[1]), "r"(a[2]), "r"(a[3]), "r"(b[0]), "r"(b[1]));
}

#define A_BYTES 10240                     // 128 rows * 80B (64 used)
#define B_BYTES 7680                      // 32 rows * 240B (224 used)
#define STAGE_BYTES (A_BYTES + B_BYTES)   // 17920
#define NBUF 3
#define EPI_STRIDE 240                    // 224B data + 16 pad per co row
#define EPI_BYTES (128 * EPI_STRIDE)      // 30720
#define SMEM_SZ (NBUF * STAGE_BYTES + EPI_BYTES)   // 84480
#define NSTAGE 16                         // 2 k * 8 kc per CTA

__device__ __forceinline__ void load_stage(int s, uint32_t sbase, int tid,
                                           int kp, int coh, int tb) {
    int k  = kp * 2 + (s >> 3);
    int kc = s & 7;
    const __half* wsrc = g_Wt + (((size_t)(k * 2 + coh) * 8 + kc) << 12);
    // A: 512 x 16B contiguous (2 per thread)
#pragma unroll
    for (int v = tid; v < 512; v += 256) {
        cp16(sbase + (v >> 2) * 80 + (v & 3) * 16, (const char*)wsrc + v * 16);
    }
    // B: 448 x 16B — 32 ci rows x 224B (112 tiles fp16)
    uint32_t bbase = sbase + A_BYTES;
    const __half* usrc = g_U + (size_t)(k * C + kc * 32) * NTILE + tb * 112;
    for (int v = tid; v < 448; v += 256) {
        int row = v / 14;
        int cv  = v - row * 14;
        cp16(bbase + row * 240 + cv * 16,
             (const char*)(usrc + (size_t)row * NTILE) + cv * 16);
    }
}

// write the 128x112 M tile from acc regs through smem with coalesced STG
__device__ __forceinline__ void epilogue_k(float acc[2][7][4], uint32_t epi,
                                           int tid, int lane, int wm, int wn,
                                           int k, int coh, int tb) {
    const int rq = lane >> 2;
    const int cq = (lane & 3) * 2;
#pragma unroll
    for (int m = 0; m < 2; ++m)
#pragma unroll
        for (int n = 0; n < 7; ++n) {
            int co  = wm * 32 + m * 16 + rq;
            int col = wn * 56 + n * 8 + cq;      // col in HALFS (fix vs round 12)
            asm volatile("st.shared.b32 [%0], %1;" ::
                "r"(epi + co * EPI_STRIDE + col * 2),
                "r"(h2_as_u32(__floats2half2_rn(acc[m][n][0], acc[m][n][1]))) : "memory");
            asm volatile("st.shared.b32 [%0], %1;" ::
                "r"(epi + (co + 8) * EPI_STRIDE + col * 2),
                "r"(h2_as_u32(__floats2half2_rn(acc[m][n][2], acc[m][n][3]))) : "memory");
        }
    __syncthreads();
    // cooperative coalesced store: thread t -> co = t>>1, half = t&1 (112B each)
    {
        int co   = tid >> 1;
        int half = tid & 1;
        uint32_t src = epi + co * EPI_STRIDE + half * 112;
        __half* dst = g_M + (size_t)(k * C + coh * 128 + co) * NTILE
                    + tb * 112 + half * 56;
#pragma unroll
        for (int c = 0; c < 7; ++c) {
            uint4 v;
            asm volatile("ld.shared.v4.b32 {%0,%1,%2,%3}, [%4];"
                         : "=r"(v.x), "=r"(v.y), "=r"(v.z), "=r"(v.w)
                         : "r"(src + c * 16));
            *(uint4*)((char*)dst + c * 16) = v;
        }
    }
    __syncthreads();   // epi reusable for the next flush
}

__global__ __launch_bounds__(256, 2) void wino_gemm_kernel() {
    extern __shared__ __align__(16) unsigned char smbuf[];
    const uint32_t sb  = smem_u32(smbuf);
    const uint32_t epi = sb + NBUF * STAGE_BYTES;
    const int tid  = threadIdx.x;
    const int lane = tid & 31;
    const int wid  = tid >> 5;
    const int wm   = wid & 3;       // 4 M-warps x 32 co
    const int wn   = wid >> 2;      // 2 N-warps x 56 tiles
    const int tb   = blockIdx.x;    // 0..111 (112-tile blocks)
    const int kp   = blockIdx.y >> 1;   // k-pair 0..7
    const int coh  = blockIdx.y & 1;

    float acc[2][7][4];
#pragma unroll
    for (int m = 0; m < 2; ++m)
#pragma unroll
        for (int n = 0; n < 7; ++n)
#pragma unroll
            for (int q = 0; q < 4; ++q) acc[m][n][q] = 0.0f;

    // hoisted fragment base addresses (buffer 0)
    uint32_t aA0[2], aB0[7];
#pragma unroll
    for (int m = 0; m < 2; ++m)
        aA0[m] = sb + (wm * 32 + m * 16 + (lane & 15)) * 80 + (lane >> 4) * 16;
#pragma unroll
    for (int n = 0; n < 7; ++n)
        aB0[n] = sb + A_BYTES + (lane & 15) * 240 + wn * 112 + n * 16;   // BYTES

    load_stage(0, sb, tid, kp, coh, tb);
    cp_commit();
    load_stage(1, sb + STAGE_BYTES, tid, kp, coh, tb);
    cp_commit();

    int buf = 0;
    for (int i = 0; i < NSTAGE; ++i) {
        asm volatile("cp.async.wait_group 1;" ::: "memory");
        __syncthreads();
        if (i + 2 < NSTAGE) {
            int nb = buf + 2; if (nb >= NBUF) nb -= NBUF;
            load_stage(i + 2, sb + nb * STAGE_BYTES, tid, kp, coh, tb);
        }
        cp_commit();

        const uint32_t off = buf * STAGE_BYTES;
#pragma unroll
        for (int ks = 0; ks < 2; ++ks) {
            uint32_t a[2][4], b[7][2];
#pragma unroll
            for (int m = 0; m < 2; ++m) ldsm_x4(a[m], aA0[m] + off + ks * 32);
#pragma unroll
            for (int n = 0; n < 7; ++n) ldsm_x2t(b[n], aB0[n] + off + ks * 16 * 240);
#pragma unroll
            for (int m = 0; m < 2; ++m)
#pragma unroll
                for (int n = 0; n < 7; ++n) mma16816(acc[m][n], a[m], b[n]);
        }

        if (i == 7) {
            // flush k0, reset acc (stage buffers untouched; epi is separate)
            epilogue_k(acc, epi, tid, lane, wm, wn, kp * 2, coh, tb);
#pragma unroll
            for (int m = 0; m < 2; ++m)
#pragma unroll
                for (int n = 0; n < 7; ++n)
#pragma unroll
                    for (int q = 0; q < 4; ++q) acc[m][n][q] = 0.0f;
        }

        ++buf; if (buf >= NBUF) buf = 0;
    }

    epilogue_k(acc, epi, tid, lane, wm, wn, kp * 2 + 1, coh, tb);
}

// ---------------- inverse transform: y = A^T M A, 2 tiles per thread --------
__global__ void wino_out_kernel(float* __restrict__ out) {
    int p = blockIdx.x * 128 + threadIdx.x;    // 0..6271 tile-pairs, grid.x = 49
    int co = blockIdx.y;
    int ty = p / 56, px = p - ty * 56;
    size_t t0 = (size_t)ty * TW + px * 2;
    float ma[4][4], mb[4][4];
#pragma unroll
    for (int k = 0; k < 16; ++k) {
        __half2 v = *(const __half2*)&g_M[(size_t)(k * C + co) * NTILE + t0];
        float2 f = __half22float2(v);
        ma[k >> 2][k & 3] = f.x;
        mb[k >> 2][k & 3] = f.y;
    }
    float4 row0, row1;
    {
        float r0[4], r1[4];
#pragma unroll
        for (int c = 0; c < 4; ++c) {
            r0[c] = ma[0][c] + ma[1][c] + ma[2][c];
            r1[c] = ma[1][c] - ma[2][c] - ma[3][c];
        }
        row0.x = r0[0] + r0[1] + r0[2];
        row0.y = r0[1] - r0[2] - r0[3];
        row1.x = r1[0] + r1[1] + r1[2];
        row1.y = r1[1] - r1[2] - r1[3];
    }
    {
        float r0[4], r1[4];
#pragma unroll
        for (int c = 0; c < 4; ++c) {
            r0[c] = mb[0][c] + mb[1][c] + mb[2][c];
            r1[c] = mb[1][c] - mb[2][c] - mb[3][c];
        }
        row0.z = r0[0] + r0[1] + r0[2];
        row0.w = r0[1] - r0[2] - r0[3];
        row1.z = r1[0] + r1[1] + r1[2];
        row1.w = r1[1] - r1[2] - r1[3];
    }
    float* pp = out + ((size_t)co * H + 2 * ty) * W + 4 * px;
    *(float4*)pp       = row0;
    *(float4*)(pp + W) = row1;
}

extern "C" void kernel_launch(void* const* d_in, const int* in_sizes, int n_in,
                              void* d_out, int out_size) {
    const float* x = (const float*)d_in[0];   // [1,256,224,224]
    const float* w = (const float*)d_in[1];   // [256,256,3,3]
    float* out = (float*)d_out;               // [256,224,224]
    (void)in_sizes; (void)n_in; (void)out_size;

    wino_w_kernel<<<(C * C + 255) / 256, 256>>>(w);
    wino_in_kernel<<<dim3(49, C), 128>>>(x);

    static int smem_set = 0;
    if (!smem_set) {
        cudaFuncSetAttribute(wino_gemm_kernel,
                             cudaFuncAttributeMaxDynamicSharedMemorySize, SMEM_SZ);
        smem_set = 1;
    }
    wino_gemm_kernel<<<dim3(TW, 16), 256, SMEM_SZ>>>();   // 112 x (8 kp * 2 coh)
    wino_out_kernel<<<dim3(49, C), 128>>>(out);
}